// round 13
// baseline (speedup 1.0000x reference)
#include <cuda_runtime.h>
#include <cuda_fp16.h>
#include <cstdint>
#include <math.h>

// ---------------------------------------------------------------------------
// KANConv2d: silu + 8 uniform cubic B-spline basis channels per input channel
// -> single 3x3 conv as implicit GEMM (mma.sync fp16, fp32 acc).
// NEW: A (feature) tiles are computed IN-KERNEL per chunk on the idle fma
// pipe (no feature pre-pass, no F global buffer, no border kernel).
// 128 CTAs x (M128,N128), 512 threads, 16 warps x 32x32 tiles,
// 6-stage pipeline (B via cp.async, A via compute+store), barrier per 128-K.
// ---------------------------------------------------------------------------

#define BATCH 4
#define CIN 64
#define OUTC 128
#define CF 576          // 64 ch * 9 feats
#define KTOT 5184       // 9 taps * 576
#define NCHUNK 81       // 5184 / 64
#define NSTAGE 6

// device scratch (allocation-free): folded weights only
__device__ __align__(16) __half g_Bf[OUTC * KTOT];

// ---------------------------------------------------------------------------
__device__ __forceinline__ uint32_t smem_u32(const void* p) {
    uint32_t a;
    asm("{ .reg .u64 t; cvta.to.shared.u64 t, %1; cvt.u32.u64 %0, t; }"
        : "=r"(a) : "l"(p));
    return a;
}

#define CP16(dst, src) \
    asm volatile("cp.async.cg.shared.global [%0], [%1], 16;" \
                 :: "r"(dst), "l"(src) : "memory")
#define CP_COMMIT() asm volatile("cp.async.commit_group;" ::: "memory")
#define CP_WAIT(n)  asm volatile("cp.async.wait_group %0;" :: "n"(n) : "memory")

#define LDSM4(r0, r1, r2, r3, a) \
    asm volatile("ldmatrix.sync.aligned.m8n8.x4.shared.b16 {%0,%1,%2,%3}, [%4];" \
                 : "=r"(r0), "=r"(r1), "=r"(r2), "=r"(r3) : "r"(a))

#define MMA16816(d, a, b0, b1) \
    asm volatile("mma.sync.aligned.m16n8k16.row.col.f32.f16.f16.f32 " \
                 "{%0,%1,%2,%3}, {%4,%5,%6,%7}, {%8,%9}, {%0,%1,%2,%3};" \
                 : "+f"((d)[0]), "+f"((d)[1]), "+f"((d)[2]), "+f"((d)[3]) \
                 : "r"((a)[0]), "r"((a)[1]), "r"((a)[2]), "r"((a)[3]), \
                   "r"(b0), "r"(b1))

#define STS16(ad, hv) \
    asm volatile("st.shared.u16 [%0], %1;" :: "r"(ad), "h"(hv))

// ---------------------------------------------------------------------------
// weight fold -> [o][kk], kk = tap*576 + c*9 + ck, source index d = c*9 + tap
// ---------------------------------------------------------------------------
__global__ __launch_bounds__(256) void weight_kernel(
    const float* __restrict__ bw, const float* __restrict__ sw,
    const float* __restrict__ ss) {
    int idx = blockIdx.x * 256 + threadIdx.x;
    if (idx >= OUTC * KTOT) return;
    int o   = idx / KTOT;
    int kk  = idx - o * KTOT;
    int tap = kk / 576;
    int r   = kk - tap * 576;
    int c   = r / 9;
    int ck  = r - c * 9;
    int d   = c * 9 + tap;
    float v = ck ? sw[(o * 576 + d) * 8 + (ck - 1)] * ss[o * 576 + d]
                 : bw[o * 576 + d];
    g_Bf[idx] = __float2half_rn(v);
}

// ---------------------------------------------------------------------------
// GEMM + fused feature computation.
// Stage (32KB): [A 16K][B 16K], 128B rows, XOR-swizzled; 6 stages.
// ---------------------------------------------------------------------------
#define STAGE_BYTES 32768
#define T_A 0
#define T_B 16384

__global__ __launch_bounds__(512, 1) void gemm_kernel(
    const float* __restrict__ x, float* __restrict__ out) {
    extern __shared__ char dynsm[];
    uint32_t raw  = smem_u32(dynsm);
    uint32_t base = (raw + 1023u) & ~1023u;

    const int tid  = threadIdx.x;
    const int wid  = tid >> 5;
    const int lane = tid & 31;
    const int wm   = wid & 3;
    const int wn   = wid >> 2;
    const int mbase = blockIdx.x * 128;

    const int b_   = mbase >> 12;          // batch
    const int oy0  = (mbase >> 6) & 63;    // first of the CTA's 2 image rows

    // ---- B cp.async mapping: brow = tid>>2 (0..127), bseg = tid&3 ----
    const int brow = tid >> 2;
    const int bseg = tid & 3;
    const __half* bp = g_Bf + (size_t)brow * KTOT;
    const uint32_t bterm = (uint32_t)brow * 128;
    const uint32_t bpat  = ((uint32_t)brow & 7) << 4;

    auto load_B = [&](int kc, int stage) {
        int boff = kc * 64 + bseg * 16;
        const char* sB = (const char*)(bp + boff);
        uint32_t sb = base + (uint32_t)stage * STAGE_BYTES + T_B + bterm;
#pragma unroll
        for (int q = 0; q < 2; q++) {
            uint32_t kb = (uint32_t)(bseg * 32 + q * 16);
            CP16(sb + (kb ^ bpat), sB + q * 16);
        }
        CP_COMMIT();
    };

    // ---- A fill: load x for chunk kc (2 values per thread) ----
    auto loadx2 = [&](int kc, float& v0, float& v1) {
        int t   = kc / 9;
        int sub = kc - 9 * t;
        int c_lo = (sub * 64) / 9;
        int kh = t / 3;
        int kwv = t - kh * 3;
#pragma unroll
        for (int tau = 0; tau < 2; tau++) {
            int e  = tau * 512 + tid;
            int px = e & 127, ci = e >> 7;
            int ch = c_lo + ci;
            int yp = oy0 + (px >> 6) + kh - 1;
            int xp = (px & 63) + kwv - 1;
            float v = 0.0f;
            if ((unsigned)yp < 64u && (unsigned)xp < 64u)
                v = __ldg(&x[(((b_ * 64 + ch) << 6) + yp) * 64 + xp]);
            if (tau == 0) v0 = v; else v1 = v;
        }
    };

    // ---- A fill: compute features & store chunk kc into stage's A half ----
    auto fill_store = [&](int kc, int stage, float v0, float v1) {
        int t   = kc / 9;
        int sub = kc - 9 * t;
        int r0  = sub * 64;
        int c_lo = r0 / 9;
        uint32_t sa = base + (uint32_t)stage * STAGE_BYTES + T_A;
#pragma unroll
        for (int tau = 0; tau < 2; tau++) {
            float v = tau ? v1 : v0;
            int e  = tau * 512 + tid;
            int px = e & 127, ci = e >> 7;
            int ch = c_lo + ci;
            int bk = ch * 9 - r0;          // chunk-local slot of this ch's q=0
            uint32_t rowb = sa + (uint32_t)px * 128;
            uint32_t pat  = ((uint32_t)px & 7) << 4;

            float sl = v / (1.0f + __expf(-v));
            unsigned short hsl = __half_as_ushort(__float2half_rn(sl));
            float s = (v + 2.2f) * 2.5f;
            int j = (int)floorf(s);

            // pass 1: silu at q=0, zeros at q=1..8 (in-window slots only)
#pragma unroll
            for (int q = 0; q < 9; q++) {
                int kloc = bk + q;
                if ((unsigned)kloc < 64u) {
                    unsigned short hv = (q == 0) ? hsl : (unsigned short)0;
                    uint32_t ad = rowb + (((uint32_t)(kloc * 2)) ^ pat);
                    STS16(ad, hv);
                }
            }
            // pass 2: overwrite the 4 nonzero basis slots (q = j-2 .. j+1)
            if (j >= 0 && j <= 10) {
                float u  = (v - (0.4f * (float)j - 2.2f)) * 2.5f;
                float um = 1.0f - u;
                float u2 = u * u, u3 = u2 * u;
                unsigned short h3 = __half_as_ushort(__float2half_rn(u3 * (1.0f / 6.0f)));
                unsigned short h2 = __half_as_ushort(__float2half_rn(
                    (-3.0f * u3 + 3.0f * u2 + 3.0f * u + 1.0f) * (1.0f / 6.0f)));
                unsigned short h1 = __half_as_ushort(__float2half_rn(
                    (3.0f * u3 - 6.0f * u2 + 4.0f) * (1.0f / 6.0f)));
                unsigned short h0 = __half_as_ushort(__float2half_rn(
                    um * um * um * (1.0f / 6.0f)));
#pragma unroll
                for (int m = 0; m < 4; m++) {
                    int qq = j + 1 - m;
                    unsigned short hv = (m == 0) ? h3 : (m == 1) ? h2
                                      : (m == 2) ? h1 : h0;
                    if (qq >= 1 && qq <= 8) {
                        int kloc = bk + qq;
                        if ((unsigned)kloc < 64u) {
                            uint32_t ad = rowb + (((uint32_t)(kloc * 2)) ^ pat);
                            STS16(ad, hv);
                        }
                    }
                }
            }
        }
    };

    // ---- ldmatrix lane addressing (32x32 warp tiles) ----
    const int rA  = lane & 15;
    const uint32_t kA = ((uint32_t)(lane >> 4)) * 16;   // bytes
    uint32_t aRow[2], aPat[2];
#pragma unroll
    for (int mt = 0; mt < 2; mt++) {
        int rr = wm * 32 + mt * 16 + rA;
        aRow[mt] = (uint32_t)rr * 128;
        aPat[mt] = ((uint32_t)rr & 7) << 4;
    }
    const int rBl = (lane & 7) + ((lane >> 4) & 1) * 8;
    const uint32_t kB = ((uint32_t)((lane >> 3) & 1)) * 16;
    uint32_t bRow[2], bPat[2];
#pragma unroll
    for (int nt = 0; nt < 2; nt++) {
        int rr = wn * 32 + nt * 16 + rBl;
        bRow[nt] = (uint32_t)rr * 128;
        bPat[nt] = ((uint32_t)rr & 7) << 4;
    }

    float acc[2][4][4];
#pragma unroll
    for (int i = 0; i < 2; i++)
#pragma unroll
        for (int j = 0; j < 4; j++)
#pragma unroll
            for (int q = 0; q < 4; q++) acc[i][j][q] = 0.0f;

    auto compute_chunk = [&](uint32_t stg) {
        const uint32_t bb = base + stg * STAGE_BYTES;
#pragma unroll
        for (int kk = 0; kk < 4; kk++) {
            uint32_t af[2][4];
#pragma unroll
            for (int mt = 0; mt < 2; mt++) {
                uint32_t addr = bb + T_A + aRow[mt] + (((uint32_t)(kk * 32) + kA) ^ aPat[mt]);
                LDSM4(af[mt][0], af[mt][1], af[mt][2], af[mt][3], addr);
            }
#pragma unroll
            for (int nt = 0; nt < 2; nt++) {
                uint32_t addr = bb + T_B + bRow[nt] + (((uint32_t)(kk * 32) + kB) ^ bPat[nt]);
                uint32_t bf[4];
                LDSM4(bf[0], bf[1], bf[2], bf[3], addr);
#pragma unroll
                for (int mt = 0; mt < 2; mt++) {
#pragma unroll
                    for (int sub = 0; sub < 2; sub++) {
                        MMA16816(acc[mt][nt * 2 + sub], af[mt],
                                 bf[sub * 2], bf[sub * 2 + 1]);
                    }
                }
            }
        }
    };

    // prologue: chunks 0..3 (B via cp.async, A via direct fill)
#pragma unroll
    for (int s = 0; s < 4; s++) load_B(s, s);
#pragma unroll
    for (int s = 0; s < 4; s++) {
        float v0, v1;
        loadx2(s, v0, v1);
        fill_store(s, s, v0, v1);
    }

    // mainloop: 40 iterations x 2 chunks; chunk c lives in stage c % 6
    int s0 = 0;
    for (int it = 0; it < 40; it++) {
        const int c0 = it * 2;
        CP_WAIT(2);
        __syncthreads();

        const int ls0 = (s0 >= 2) ? s0 - 2 : s0 + 4;   // (s0+4) mod 6
        const int ls1 = (ls0 + 1 == 6) ? 0 : ls0 + 1;
        const bool p4 = (c0 + 4 < NCHUNK);
        const bool p5 = (c0 + 5 < NCHUNK);
        if (p4) load_B(c0 + 4, ls0); else CP_COMMIT();
        if (p5) load_B(c0 + 5, ls1); else CP_COMMIT();

        // issue x loads for both future A fills early (hide L2 latency)
        float va0 = 0.f, va1 = 0.f, vb0 = 0.f, vb1 = 0.f;
        if (p4) loadx2(c0 + 4, va0, va1);
        if (p5) loadx2(c0 + 5, vb0, vb1);

        compute_chunk((uint32_t)s0);
        if (p4) fill_store(c0 + 4, ls0, va0, va1);
        compute_chunk((uint32_t)(s0 + 1));
        if (p5) fill_store(c0 + 5, ls1, vb0, vb1);

        s0 += 2; if (s0 == 6) s0 = 0;
    }
    // final chunk 80 (stage 80 % 6 == 2 == s0 here)
    CP_WAIT(0);
    __syncthreads();
    compute_chunk((uint32_t)s0);
    __syncthreads();

    // ---- epilogue: stage through smem (transpose), coalesced global write --
    float* st = reinterpret_cast<float*>(dynsm + (base - raw));
    const int g  = lane >> 2;
    const int tg = lane & 3;
#pragma unroll
    for (int mt = 0; mt < 2; mt++) {
#pragma unroll
        for (int n8 = 0; n8 < 4; n8++) {
            int m0 = wm * 32 + mt * 16 + g;
            int n0 = wn * 32 + n8 * 8 + tg * 2;
            const float* c = acc[mt][n8];
            st[m0 * 129 + n0]           = c[0];
            st[m0 * 129 + n0 + 1]       = c[1];
            st[(m0 + 8) * 129 + n0]     = c[2];
            st[(m0 + 8) * 129 + n0 + 1] = c[3];
        }
    }
    __syncthreads();

    const int spb = mbase & 4095;
#pragma unroll
    for (int r = 0; r < 32; r++) {
        int idx = r * 512 + tid;
        int o = idx >> 7;
        int m = idx & 127;
        out[(((size_t)(b_ * OUTC + o)) << 12) + spb + m] = st[m * 129 + o];
    }
}

// ---------------------------------------------------------------------------
extern "C" void kernel_launch(void* const* d_in, const int* in_sizes, int n_in,
                              void* d_out, int out_size) {
    const float* x  = (const float*)d_in[0];
    const float* bw = (const float*)d_in[1];
    const float* sw = (const float*)d_in[2];
    const float* ss = (const float*)d_in[3];
    float* out = (float*)d_out;

    cudaFuncSetAttribute(gemm_kernel, cudaFuncAttributeMaxDynamicSharedMemorySize, 197632);

    weight_kernel<<<(OUTC * KTOT + 255) / 256, 256>>>(bw, sw, ss);
    gemm_kernel<<<128, 512, 197632>>>(x, out);
}

// round 14
// speedup vs baseline: 1.0096x; 1.0096x over previous
#include <cuda_runtime.h>
#include <cuda_fp16.h>
#include <cstdint>
#include <math.h>

// ---------------------------------------------------------------------------
// KANConv2d: silu + 8 uniform cubic B-spline basis channels per input channel
// -> single 3x3 conv as implicit GEMM (mma.sync fp16, fp32 acc).
// NEW: A (feature) tiles are computed IN-KERNEL per chunk on the idle fma
// pipe (no feature pre-pass, no F global buffer, no border kernel).
// 128 CTAs x (M128,N128), 512 threads, 16 warps x 32x32 tiles,
// 6-stage pipeline (B via cp.async, A via compute+store), barrier per 128-K.
// ---------------------------------------------------------------------------

#define BATCH 4
#define CIN 64
#define OUTC 128
#define CF 576          // 64 ch * 9 feats
#define KTOT 5184       // 9 taps * 576
#define NCHUNK 81       // 5184 / 64
#define NSTAGE 6

// device scratch (allocation-free): folded weights only
__device__ __align__(16) __half g_Bf[OUTC * KTOT];

// ---------------------------------------------------------------------------
__device__ __forceinline__ uint32_t smem_u32(const void* p) {
    uint32_t a;
    asm("{ .reg .u64 t; cvta.to.shared.u64 t, %1; cvt.u32.u64 %0, t; }"
        : "=r"(a) : "l"(p));
    return a;
}

#define CP16(dst, src) \
    asm volatile("cp.async.cg.shared.global [%0], [%1], 16;" \
                 :: "r"(dst), "l"(src) : "memory")
#define CP_COMMIT() asm volatile("cp.async.commit_group;" ::: "memory")
#define CP_WAIT(n)  asm volatile("cp.async.wait_group %0;" :: "n"(n) : "memory")

#define LDSM4(r0, r1, r2, r3, a) \
    asm volatile("ldmatrix.sync.aligned.m8n8.x4.shared.b16 {%0,%1,%2,%3}, [%4];" \
                 : "=r"(r0), "=r"(r1), "=r"(r2), "=r"(r3) : "r"(a))

#define MMA16816(d, a, b0, b1) \
    asm volatile("mma.sync.aligned.m16n8k16.row.col.f32.f16.f16.f32 " \
                 "{%0,%1,%2,%3}, {%4,%5,%6,%7}, {%8,%9}, {%0,%1,%2,%3};" \
                 : "+f"((d)[0]), "+f"((d)[1]), "+f"((d)[2]), "+f"((d)[3]) \
                 : "r"((a)[0]), "r"((a)[1]), "r"((a)[2]), "r"((a)[3]), \
                   "r"(b0), "r"(b1))

#define STS16(ad, hv) \
    asm volatile("st.shared.u16 [%0], %1;" :: "r"(ad), "h"(hv))

// ---------------------------------------------------------------------------
// weight fold -> [o][kk], kk = tap*576 + c*9 + ck, source index d = c*9 + tap
// ---------------------------------------------------------------------------
__global__ __launch_bounds__(256) void weight_kernel(
    const float* __restrict__ bw, const float* __restrict__ sw,
    const float* __restrict__ ss) {
    int idx = blockIdx.x * 256 + threadIdx.x;
    if (idx >= OUTC * KTOT) return;
    int o   = idx / KTOT;
    int kk  = idx - o * KTOT;
    int tap = kk / 576;
    int r   = kk - tap * 576;
    int c   = r / 9;
    int ck  = r - c * 9;
    int d   = c * 9 + tap;
    float v = ck ? sw[(o * 576 + d) * 8 + (ck - 1)] * ss[o * 576 + d]
                 : bw[o * 576 + d];
    g_Bf[idx] = __float2half_rn(v);
}

// ---------------------------------------------------------------------------
// GEMM + fused feature computation.
// Stage (32KB): [A 16K][B 16K], 128B rows, XOR-swizzled; 6 stages.
// ---------------------------------------------------------------------------
#define STAGE_BYTES 32768
#define T_A 0
#define T_B 16384

__global__ __launch_bounds__(512, 1) void gemm_kernel(
    const float* __restrict__ x, float* __restrict__ out) {
    extern __shared__ char dynsm[];
    uint32_t raw  = smem_u32(dynsm);
    uint32_t base = (raw + 1023u) & ~1023u;

    const int tid  = threadIdx.x;
    const int wid  = tid >> 5;
    const int lane = tid & 31;
    const int wm   = wid & 3;
    const int wn   = wid >> 2;
    const int mbase = blockIdx.x * 128;

    const int b_   = mbase >> 12;          // batch
    const int oy0  = (mbase >> 6) & 63;    // first of the CTA's 2 image rows

    // ---- B cp.async mapping: brow = tid>>2 (0..127), bseg = tid&3 ----
    const int brow = tid >> 2;
    const int bseg = tid & 3;
    const __half* bp = g_Bf + (size_t)brow * KTOT;
    const uint32_t bterm = (uint32_t)brow * 128;
    const uint32_t bpat  = ((uint32_t)brow & 7) << 4;

    auto load_B = [&](int kc, int stage) {
        int boff = kc * 64 + bseg * 16;
        const char* sB = (const char*)(bp + boff);
        uint32_t sb = base + (uint32_t)stage * STAGE_BYTES + T_B + bterm;
#pragma unroll
        for (int q = 0; q < 2; q++) {
            uint32_t kb = (uint32_t)(bseg * 32 + q * 16);
            CP16(sb + (kb ^ bpat), sB + q * 16);
        }
        CP_COMMIT();
    };

    // ---- A fill: load x for chunk kc (2 values per thread) ----
    auto loadx2 = [&](int kc, float& v0, float& v1) {
        int t   = kc / 9;
        int sub = kc - 9 * t;
        int c_lo = (sub * 64) / 9;
        int kh = t / 3;
        int kwv = t - kh * 3;
#pragma unroll
        for (int tau = 0; tau < 2; tau++) {
            int e  = tau * 512 + tid;
            int px = e & 127, ci = e >> 7;
            int ch = c_lo + ci;
            int yp = oy0 + (px >> 6) + kh - 1;
            int xp = (px & 63) + kwv - 1;
            float v = 0.0f;
            if ((unsigned)yp < 64u && (unsigned)xp < 64u)
                v = __ldg(&x[(((b_ * 64 + ch) << 6) + yp) * 64 + xp]);
            if (tau == 0) v0 = v; else v1 = v;
        }
    };

    // ---- A fill: compute features & store chunk kc into stage's A half ----
    auto fill_store = [&](int kc, int stage, float v0, float v1) {
        int t   = kc / 9;
        int sub = kc - 9 * t;
        int r0  = sub * 64;
        int c_lo = r0 / 9;
        uint32_t sa = base + (uint32_t)stage * STAGE_BYTES + T_A;
#pragma unroll
        for (int tau = 0; tau < 2; tau++) {
            float v = tau ? v1 : v0;
            int e  = tau * 512 + tid;
            int px = e & 127, ci = e >> 7;
            int ch = c_lo + ci;
            int bk = ch * 9 - r0;          // chunk-local slot of this ch's q=0
            uint32_t rowb = sa + (uint32_t)px * 128;
            uint32_t pat  = ((uint32_t)px & 7) << 4;

            float sl = v / (1.0f + __expf(-v));
            unsigned short hsl = __half_as_ushort(__float2half_rn(sl));
            float s = (v + 2.2f) * 2.5f;
            int j = (int)floorf(s);

            // pass 1: silu at q=0, zeros at q=1..8 (in-window slots only)
#pragma unroll
            for (int q = 0; q < 9; q++) {
                int kloc = bk + q;
                if ((unsigned)kloc < 64u) {
                    unsigned short hv = (q == 0) ? hsl : (unsigned short)0;
                    uint32_t ad = rowb + (((uint32_t)(kloc * 2)) ^ pat);
                    STS16(ad, hv);
                }
            }
            // pass 2: overwrite the 4 nonzero basis slots (q = j-2 .. j+1)
            if (j >= 0 && j <= 10) {
                float u  = (v - (0.4f * (float)j - 2.2f)) * 2.5f;
                float um = 1.0f - u;
                float u2 = u * u, u3 = u2 * u;
                unsigned short h3 = __half_as_ushort(__float2half_rn(u3 * (1.0f / 6.0f)));
                unsigned short h2 = __half_as_ushort(__float2half_rn(
                    (-3.0f * u3 + 3.0f * u2 + 3.0f * u + 1.0f) * (1.0f / 6.0f)));
                unsigned short h1 = __half_as_ushort(__float2half_rn(
                    (3.0f * u3 - 6.0f * u2 + 4.0f) * (1.0f / 6.0f)));
                unsigned short h0 = __half_as_ushort(__float2half_rn(
                    um * um * um * (1.0f / 6.0f)));
#pragma unroll
                for (int m = 0; m < 4; m++) {
                    int qq = j + 1 - m;
                    unsigned short hv = (m == 0) ? h3 : (m == 1) ? h2
                                      : (m == 2) ? h1 : h0;
                    if (qq >= 1 && qq <= 8) {
                        int kloc = bk + qq;
                        if ((unsigned)kloc < 64u) {
                            uint32_t ad = rowb + (((uint32_t)(kloc * 2)) ^ pat);
                            STS16(ad, hv);
                        }
                    }
                }
            }
        }
    };

    // ---- ldmatrix lane addressing (32x32 warp tiles) ----
    const int rA  = lane & 15;
    const uint32_t kA = ((uint32_t)(lane >> 4)) * 16;   // bytes
    uint32_t aRow[2], aPat[2];
#pragma unroll
    for (int mt = 0; mt < 2; mt++) {
        int rr = wm * 32 + mt * 16 + rA;
        aRow[mt] = (uint32_t)rr * 128;
        aPat[mt] = ((uint32_t)rr & 7) << 4;
    }
    const int rBl = (lane & 7) + ((lane >> 4) & 1) * 8;
    const uint32_t kB = ((uint32_t)((lane >> 3) & 1)) * 16;
    uint32_t bRow[2], bPat[2];
#pragma unroll
    for (int nt = 0; nt < 2; nt++) {
        int rr = wn * 32 + nt * 16 + rBl;
        bRow[nt] = (uint32_t)rr * 128;
        bPat[nt] = ((uint32_t)rr & 7) << 4;
    }

    float acc[2][4][4];
#pragma unroll
    for (int i = 0; i < 2; i++)
#pragma unroll
        for (int j = 0; j < 4; j++)
#pragma unroll
            for (int q = 0; q < 4; q++) acc[i][j][q] = 0.0f;

    auto compute_chunk = [&](uint32_t stg) {
        const uint32_t bb = base + stg * STAGE_BYTES;
#pragma unroll
        for (int kk = 0; kk < 4; kk++) {
            uint32_t af[2][4];
#pragma unroll
            for (int mt = 0; mt < 2; mt++) {
                uint32_t addr = bb + T_A + aRow[mt] + (((uint32_t)(kk * 32) + kA) ^ aPat[mt]);
                LDSM4(af[mt][0], af[mt][1], af[mt][2], af[mt][3], addr);
            }
#pragma unroll
            for (int nt = 0; nt < 2; nt++) {
                uint32_t addr = bb + T_B + bRow[nt] + (((uint32_t)(kk * 32) + kB) ^ bPat[nt]);
                uint32_t bf[4];
                LDSM4(bf[0], bf[1], bf[2], bf[3], addr);
#pragma unroll
                for (int mt = 0; mt < 2; mt++) {
#pragma unroll
                    for (int sub = 0; sub < 2; sub++) {
                        MMA16816(acc[mt][nt * 2 + sub], af[mt],
                                 bf[sub * 2], bf[sub * 2 + 1]);
                    }
                }
            }
        }
    };

    // prologue: chunks 0..3 (B via cp.async, A via direct fill)
#pragma unroll
    for (int s = 0; s < 4; s++) load_B(s, s);
#pragma unroll
    for (int s = 0; s < 4; s++) {
        float v0, v1;
        loadx2(s, v0, v1);
        fill_store(s, s, v0, v1);
    }

    // mainloop: 40 iterations x 2 chunks; chunk c lives in stage c % 6
    int s0 = 0;
    for (int it = 0; it < 40; it++) {
        const int c0 = it * 2;
        CP_WAIT(2);
        __syncthreads();

        const int ls0 = (s0 >= 2) ? s0 - 2 : s0 + 4;   // (s0+4) mod 6
        const int ls1 = (ls0 + 1 == 6) ? 0 : ls0 + 1;
        const bool p4 = (c0 + 4 < NCHUNK);
        const bool p5 = (c0 + 5 < NCHUNK);
        if (p4) load_B(c0 + 4, ls0); else CP_COMMIT();
        if (p5) load_B(c0 + 5, ls1); else CP_COMMIT();

        // issue x loads for both future A fills early (hide L2 latency)
        float va0 = 0.f, va1 = 0.f, vb0 = 0.f, vb1 = 0.f;
        if (p4) loadx2(c0 + 4, va0, va1);
        if (p5) loadx2(c0 + 5, vb0, vb1);

        compute_chunk((uint32_t)s0);
        if (p4) fill_store(c0 + 4, ls0, va0, va1);
        compute_chunk((uint32_t)(s0 + 1));
        if (p5) fill_store(c0 + 5, ls1, vb0, vb1);

        s0 += 2; if (s0 == 6) s0 = 0;
    }
    // final chunk 80 (stage 80 % 6 == 2 == s0 here)
    CP_WAIT(0);
    __syncthreads();
    compute_chunk((uint32_t)s0);
    __syncthreads();

    // ---- epilogue: stage through smem (transpose), coalesced global write --
    float* st = reinterpret_cast<float*>(dynsm + (base - raw));
    const int g  = lane >> 2;
    const int tg = lane & 3;
#pragma unroll
    for (int mt = 0; mt < 2; mt++) {
#pragma unroll
        for (int n8 = 0; n8 < 4; n8++) {
            int m0 = wm * 32 + mt * 16 + g;
            int n0 = wn * 32 + n8 * 8 + tg * 2;
            const float* c = acc[mt][n8];
            st[m0 * 129 + n0]           = c[0];
            st[m0 * 129 + n0 + 1]       = c[1];
            st[(m0 + 8) * 129 + n0]     = c[2];
            st[(m0 + 8) * 129 + n0 + 1] = c[3];
        }
    }
    __syncthreads();

    const int spb = mbase & 4095;
#pragma unroll
    for (int r = 0; r < 32; r++) {
        int idx = r * 512 + tid;
        int o = idx >> 7;
        int m = idx & 127;
        out[(((size_t)(b_ * OUTC + o)) << 12) + spb + m] = st[m * 129 + o];
    }
}

// ---------------------------------------------------------------------------
extern "C" void kernel_launch(void* const* d_in, const int* in_sizes, int n_in,
                              void* d_out, int out_size) {
    const float* x  = (const float*)d_in[0];
    const float* bw = (const float*)d_in[1];
    const float* sw = (const float*)d_in[2];
    const float* ss = (const float*)d_in[3];
    float* out = (float*)d_out;

    cudaFuncSetAttribute(gemm_kernel, cudaFuncAttributeMaxDynamicSharedMemorySize, 197632);

    weight_kernel<<<(OUTC * KTOT + 255) / 256, 256>>>(bw, sw, ss);
    gemm_kernel<<<128, 512, 197632>>>(x, out);
}